// round 2
// baseline (speedup 1.0000x reference)
#include <cuda_runtime.h>
#include <cstdint>
#include <cstddef>

#define BATCH   8
#define NPTS    4096
#define NPOINT  1024
#define NSAMPLE 32
#define CFEAT   64
#define K0PAD   72      // 67 channels padded to 72 (16B-aligned rows, mult of 8)
#define EPSV    1e-5f

constexpr int M_TOTAL = BATCH * NPOINT * NSAMPLE;   // 262144
constexpr int NEWXYZ  = BATCH * NPOINT * 3;         // 24576
constexpr int NSTATB  = 1024;                       // stats partial blocks

// ---------------- device scratch (static: no allocations allowed) ----------------
__device__ float g_X0[(size_t)M_TOTAL * K0PAD];     // grouped input, padded K
__device__ float g_Y0[(size_t)M_TOTAL * 64];        // raw conv0 out
__device__ float g_Y1[(size_t)M_TOTAL * 128];       // raw conv1 out
__device__ float g_Y2[(size_t)M_TOTAL * 256];       // raw conv2 out
__device__ float g_part[2][256 * NSTATB];           // per-block [sum, sumsq] partials
__device__ float g_scale[256];                      // BN fused scale (current layer)
__device__ float g_shift[256];                      // BN fused shift (current layer)

// ---------------- small helpers ----------------
__device__ __forceinline__ uint32_t cvt_tf32(float x) {
    uint32_t r; asm("cvt.rna.tf32.f32 %0, %1;" : "=r"(r) : "f"(x)); return r;
}
__device__ __forceinline__ void mma_tf32(float d[4], const uint32_t a[4], const uint32_t b[2]) {
    asm volatile("mma.sync.aligned.m16n8k8.row.col.f32.tf32.tf32.f32 "
                 "{%0,%1,%2,%3}, {%4,%5,%6,%7}, {%8,%9}, {%0,%1,%2,%3};"
                 : "+f"(d[0]), "+f"(d[1]), "+f"(d[2]), "+f"(d[3])
                 : "r"(a[0]), "r"(a[1]), "r"(a[2]), "r"(a[3]),
                   "r"(b[0]), "r"(b[1]));
}

// ---------------- KNN (32 smallest d2, stable-argsort tiebreak) + gather ----------------
__global__ void knn_gather_kernel(const float* __restrict__ xyz,
                                  const float* __restrict__ pts,
                                  const int*   __restrict__ fps,
                                  float*       __restrict__ out_newxyz) {
    __shared__ float sd2[NPTS];
    __shared__ unsigned long long sred[8];
    __shared__ int sel[NSAMPLE];

    const int bn  = blockIdx.x;          // b*NPOINT + j
    const int b   = bn >> 10;
    const int tid = threadIdx.x;
    const float* xb = xyz + (size_t)b * NPTS * 3;
    const int fi = fps[bn];
    const float cx = xb[fi * 3 + 0];
    const float cy = xb[fi * 3 + 1];
    const float cz = xb[fi * 3 + 2];
    if (tid == 0) {
        out_newxyz[bn * 3 + 0] = cx;
        out_newxyz[bn * 3 + 1] = cy;
        out_newxyz[bn * 3 + 2] = cz;
    }
    // exact arithmetic order to match ((dx*dx + dy*dy) + dz*dz), no FMA contraction
    for (int i = tid; i < NPTS; i += 256) {
        float dx = __fsub_rn(cx, xb[i * 3 + 0]);
        float dy = __fsub_rn(cy, xb[i * 3 + 1]);
        float dz = __fsub_rn(cz, xb[i * 3 + 2]);
        sd2[i] = __fadd_rn(__fadd_rn(__fmul_rn(dx, dx), __fmul_rn(dy, dy)), __fmul_rn(dz, dz));
    }
    __syncthreads();

    for (int r = 0; r < NSAMPLE; r++) {
        unsigned long long best = ~0ULL;
        for (int i = tid; i < NPTS; i += 256) {
            unsigned long long key =
                ((unsigned long long)__float_as_uint(sd2[i]) << 32) | (unsigned)i;
            if (key < best) best = key;
        }
        #pragma unroll
        for (int o = 16; o; o >>= 1) {
            unsigned long long other = __shfl_xor_sync(0xffffffffu, best, o);
            if (other < best) best = other;
        }
        if ((tid & 31) == 0) sred[tid >> 5] = best;
        __syncthreads();
        if (tid == 0) {
            best = sred[0];
            #pragma unroll
            for (int w = 1; w < 8; w++) if (sred[w] < best) best = sred[w];
            int idx = (int)(best & 0xffffffffu);
            sel[r] = idx;
            sd2[idx] = __int_as_float(0x7f800000);   // +inf: exclude from next rounds
        }
        __syncthreads();
    }

    // gather grouped features: [xyz(3) | points(64) | zero-pad(5)]
    const float* pb = pts + (size_t)b * NPTS * CFEAT;
    const size_t mbase = (size_t)bn * NSAMPLE;
    for (int e = tid; e < NSAMPLE * K0PAD; e += 256) {
        int s = e / K0PAD, c = e - s * K0PAD;
        int pi = sel[s];
        float v = 0.f;
        if (c < 3)              v = xb[pi * 3 + c];
        else if (c < 3 + CFEAT) v = pb[(size_t)pi * CFEAT + (c - 3)];
        g_X0[(mbase + s) * K0PAD + c] = v;
    }
}

// ---------------- TF32 tensor-core GEMM: Y[m,oc] = sum_k X[m,k] * W[oc,k] (+bias) ----------------
// Optional fused input transform: x <- relu(x*scale[k] + shift[k])  (prev layer's BN+ReLU)
// Block tile 128(m) x 64(oc), 8 warps (4m x 2n), warp tile 32x32 via m16n8k8.
template<int KTILES, bool AFF>
__global__ __launch_bounds__(256)
void gemm_tf32_kernel(const float* __restrict__ X, int ldx,
                      const float* __restrict__ W, int Kvalid,
                      const float* __restrict__ bias,
                      const float* __restrict__ scl,
                      const float* __restrict__ shf,
                      float* __restrict__ Y, int OC) {
    __shared__ uint32_t As[128][36];   // [m][k], row stride 36 (144B, 16B aligned, conflict-free)
    __shared__ uint32_t Bs[64][36];    // [oc][k]

    const int tid  = threadIdx.x;
    const int lane = tid & 31;
    const int wid  = tid >> 5;
    const int wm   = wid & 3;          // warp m index (0..3)
    const int wn   = wid >> 2;         // warp n index (0..1)
    const int m0   = blockIdx.y * 128;
    const int oc0  = blockIdx.x * 64;

    float acc[2][4][4];
    #pragma unroll
    for (int i = 0; i < 2; i++)
        #pragma unroll
        for (int j = 0; j < 4; j++)
            #pragma unroll
            for (int k = 0; k < 4; k++) acc[i][j][k] = 0.f;

    for (int kt = 0; kt < KTILES; kt++) {
        const int kbase = kt * 32;

        // --- A tile: 128 rows x 32 k, float4 loads, optional BN+ReLU, cvt->tf32 ---
        #pragma unroll
        for (int it = 0; it < 4; it++) {
            int idx = tid + it * 256;
            int row = idx >> 3;
            int q   = idx & 7;
            int kk  = kbase + q * 4;
            float4 v = make_float4(0.f, 0.f, 0.f, 0.f);
            if (kk < ldx) {
                v = *reinterpret_cast<const float4*>(X + (size_t)(m0 + row) * ldx + kk);
                if (AFF) {
                    float4 s4 = *reinterpret_cast<const float4*>(scl + kk);
                    float4 h4 = *reinterpret_cast<const float4*>(shf + kk);
                    v.x = fmaxf(fmaf(v.x, s4.x, h4.x), 0.f);
                    v.y = fmaxf(fmaf(v.y, s4.y, h4.y), 0.f);
                    v.z = fmaxf(fmaf(v.z, s4.z, h4.z), 0.f);
                    v.w = fmaxf(fmaf(v.w, s4.w, h4.w), 0.f);
                }
            }
            uint4 u;
            u.x = cvt_tf32(v.x); u.y = cvt_tf32(v.y);
            u.z = cvt_tf32(v.z); u.w = cvt_tf32(v.w);
            *reinterpret_cast<uint4*>(&As[row][q * 4]) = u;
        }
        // --- B tile: 64 oc x 32 k, scalar (K may be ragged: 67) ---
        #pragma unroll
        for (int it = 0; it < 8; it++) {
            int idx = tid + it * 256;
            int oc  = idx >> 5;
            int kw  = idx & 31;
            int kk  = kbase + kw;
            float wv = (kk < Kvalid) ? W[(size_t)(oc0 + oc) * Kvalid + kk] : 0.f;
            Bs[oc][kw] = cvt_tf32(wv);
        }
        __syncthreads();

        #pragma unroll
        for (int kc = 0; kc < 4; kc++) {
            const int ak = kc * 8 + (lane & 3);
            uint32_t a[2][4];
            #pragma unroll
            for (int mi = 0; mi < 2; mi++) {
                int r = wm * 32 + mi * 16 + (lane >> 2);
                a[mi][0] = As[r][ak];
                a[mi][1] = As[r + 8][ak];
                a[mi][2] = As[r][ak + 4];
                a[mi][3] = As[r + 8][ak + 4];
            }
            uint32_t bb[4][2];
            #pragma unroll
            for (int ni = 0; ni < 4; ni++) {
                int c = wn * 32 + ni * 8 + (lane >> 2);
                bb[ni][0] = Bs[c][ak];
                bb[ni][1] = Bs[c][ak + 4];
            }
            #pragma unroll
            for (int mi = 0; mi < 2; mi++)
                #pragma unroll
                for (int ni = 0; ni < 4; ni++)
                    mma_tf32(acc[mi][ni], a[mi], bb[ni]);
        }
        __syncthreads();
    }

    // --- epilogue: +bias, store raw (pre-BN) fp32 ---
    #pragma unroll
    for (int ni = 0; ni < 4; ni++) {
        int c = oc0 + wn * 32 + ni * 8 + 2 * (lane & 3);
        float b0 = bias[c], b1 = bias[c + 1];
        #pragma unroll
        for (int mi = 0; mi < 2; mi++) {
            int r = m0 + wm * 32 + mi * 16 + (lane >> 2);
            float2 v0 = make_float2(acc[mi][ni][0] + b0, acc[mi][ni][1] + b1);
            float2 v1 = make_float2(acc[mi][ni][2] + b0, acc[mi][ni][3] + b1);
            *reinterpret_cast<float2*>(Y + (size_t)r * OC + c)       = v0;
            *reinterpret_cast<float2*>(Y + (size_t)(r + 8) * OC + c) = v1;
        }
    }
}

// ---------------- deterministic BN stats: stage 1 (per-block partials) ----------------
template<int OC>
__global__ __launch_bounds__(256)
void stats_partial_kernel(const float* __restrict__ Y) {
    constexpr int GROUPS = 256 / OC;
    constexpr int ROWS   = M_TOTAL / NSTATB;   // 256
    const int tid = threadIdx.x;
    const int oc  = (OC == 256) ? tid : (tid % OC);
    const int g   = (OC == 256) ? 0   : (tid / OC);
    const size_t r0 = (size_t)blockIdx.x * ROWS;
    float s = 0.f, s2 = 0.f;
    for (int r = g; r < ROWS; r += GROUPS) {
        float v = Y[(r0 + r) * OC + oc];
        s += v; s2 += v * v;
    }
    if (GROUPS > 1) {
        __shared__ float sh[2][256];
        sh[0][tid] = s; sh[1][tid] = s2;
        __syncthreads();
        if (g == 0) {
            for (int gg = 1; gg < GROUPS; gg++) {
                s  += sh[0][tid + gg * OC];
                s2 += sh[1][tid + gg * OC];
            }
        }
    }
    if (g == 0) {
        g_part[0][(size_t)oc * NSTATB + blockIdx.x] = s;
        g_part[1][(size_t)oc * NSTATB + blockIdx.x] = s2;
    }
}

// ---------------- stats stage 2: mean/var -> fused scale/shift ----------------
__global__ __launch_bounds__(256)
void stats_final_kernel(const float* __restrict__ gamma, const float* __restrict__ beta) {
    const int oc  = blockIdx.x;
    const int tid = threadIdx.x;
    float s = 0.f, s2 = 0.f;
    for (int i = tid; i < NSTATB; i += 256) {
        s  += g_part[0][(size_t)oc * NSTATB + i];
        s2 += g_part[1][(size_t)oc * NSTATB + i];
    }
    __shared__ float sh[2][256];
    sh[0][tid] = s; sh[1][tid] = s2;
    __syncthreads();
    for (int off = 128; off; off >>= 1) {
        if (tid < off) {
            sh[0][tid] += sh[0][tid + off];
            sh[1][tid] += sh[1][tid + off];
        }
        __syncthreads();
    }
    if (tid == 0) {
        float inv  = 1.0f / (float)M_TOTAL;
        float mean = sh[0][0] * inv;
        float var  = sh[1][0] * inv - mean * mean;
        float sc   = gamma[oc] / sqrtf(var + EPSV);
        g_scale[oc] = sc;
        g_shift[oc] = beta[oc] - mean * sc;
    }
}

// ---------------- final BN+ReLU + max over samples ----------------
__global__ __launch_bounds__(256)
void maxpool_kernel(const float* __restrict__ Y2, float* __restrict__ outp) {
    const int bn = blockIdx.x;
    const int oc = threadIdx.x;
    const float sc = g_scale[oc], sh = g_shift[oc];
    const float* p = Y2 + (size_t)bn * NSAMPLE * 256 + oc;
    float m = -3.4e38f;
    #pragma unroll
    for (int s = 0; s < NSAMPLE; s++) {
        float v = fmaxf(fmaf(p[s * 256], sc, sh), 0.f);
        m = fmaxf(m, v);
    }
    outp[(size_t)bn * 256 + oc] = m;
}

// ---------------- launch ----------------
extern "C" void kernel_launch(void* const* d_in, const int* in_sizes, int n_in,
                              void* d_out, int out_size) {
    (void)in_sizes; (void)n_in; (void)out_size;
    const float* xyz = (const float*)d_in[0];
    const float* pts = (const float*)d_in[1];
    const int*   fps = (const int*)d_in[2];
    const float* w0  = (const float*)d_in[3];
    const float* b0  = (const float*)d_in[4];
    const float* gm0 = (const float*)d_in[5];
    const float* bt0 = (const float*)d_in[6];
    const float* w1  = (const float*)d_in[7];
    const float* b1  = (const float*)d_in[8];
    const float* gm1 = (const float*)d_in[9];
    const float* bt1 = (const float*)d_in[10];
    const float* w2  = (const float*)d_in[11];
    const float* b2  = (const float*)d_in[12];
    const float* gm2 = (const float*)d_in[13];
    const float* bt2 = (const float*)d_in[14];
    float* out = (float*)d_out;

    void *pX0, *pY0, *pY1, *pY2, *pSc, *pSh;
    cudaGetSymbolAddress(&pX0, g_X0);
    cudaGetSymbolAddress(&pY0, g_Y0);
    cudaGetSymbolAddress(&pY1, g_Y1);
    cudaGetSymbolAddress(&pY2, g_Y2);
    cudaGetSymbolAddress(&pSc, g_scale);
    cudaGetSymbolAddress(&pSh, g_shift);
    float* X0 = (float*)pX0;
    float* Y0 = (float*)pY0;
    float* Y1 = (float*)pY1;
    float* Y2 = (float*)pY2;
    const float* Sc = (const float*)pSc;
    const float* Sh = (const float*)pSh;

    // 1) KNN + gather (+ writes new_xyz to out[0:24576))
    knn_gather_kernel<<<BATCH * NPOINT, 256>>>(xyz, pts, fps, out);

    // 2) layer 0: conv (K=67 padded to 72) -> raw Y0; stats -> scale/shift
    gemm_tf32_kernel<3, false><<<dim3(1, M_TOTAL / 128), 256>>>(
        X0, K0PAD, w0, 67, b0, nullptr, nullptr, Y0, 64);
    stats_partial_kernel<64><<<NSTATB, 256>>>(Y0);
    stats_final_kernel<<<64, 256>>>(gm0, bt0);

    // 3) layer 1: fused BN0+ReLU on load, conv -> raw Y1; stats
    gemm_tf32_kernel<2, true><<<dim3(2, M_TOTAL / 128), 256>>>(
        Y0, 64, w1, 64, b1, Sc, Sh, Y1, 128);
    stats_partial_kernel<128><<<NSTATB, 256>>>(Y1);
    stats_final_kernel<<<128, 256>>>(gm1, bt1);

    // 4) layer 2: fused BN1+ReLU on load, conv -> raw Y2; stats
    gemm_tf32_kernel<4, true><<<dim3(4, M_TOTAL / 128), 256>>>(
        Y1, 128, w2, 128, b2, Sc, Sh, Y2, 256);
    stats_partial_kernel<256><<<NSTATB, 256>>>(Y2);
    stats_final_kernel<<<256, 256>>>(gm2, bt2);

    // 5) BN2+ReLU + max over 32 samples -> new_points
    maxpool_kernel<<<BATCH * NPOINT, 256>>>(Y2, out + NEWXYZ);
}